// round 9
// baseline (speedup 1.0000x reference)
#include <cuda_runtime.h>
#include <cstdint>

// Problem constants
#define BB 256
#define TT 512
#define NN 128

// ---------------- device scratch ----------------
__device__ float g_E[NN * NN];                 // exp(trans)
__device__ float g_lognorm[BB];
__device__ unsigned char g_bp[(size_t)BB * TT * NN]; // backpointers, 16.7 MB
__device__ int   g_lasttag[BB];

__device__ __forceinline__ unsigned ordf(float f) {
    unsigned u = __float_as_uint(f);
    return u ^ (((int)u >> 31) | 0x80000000u);
}
__device__ __forceinline__ float iordf(unsigned v) {
    return __uint_as_float(v ^ (0x80000000u | ~(unsigned)((int)v >> 31)));
}

__device__ __forceinline__ void ffma2(unsigned long long& d,
                                      unsigned long long a,
                                      unsigned long long b) {
    asm("fma.rn.f32x2 %0, %1, %2, %0;" : "+l"(d) : "l"(a), "l"(b));
}
__device__ __forceinline__ float lo32(unsigned long long v) {
    return __uint_as_float((unsigned)v);
}
__device__ __forceinline__ float hi32(unsigned long long v) {
    return __uint_as_float((unsigned)(v >> 32));
}

// ---------------- K0: prep -----------------------------------------
__global__ void k_prep(const float* __restrict__ trans, float* __restrict__ out_trans) {
    int idx = blockIdx.x * 256 + threadIdx.x;
    if (idx < NN * NN) {
        float v = trans[idx];
        g_E[idx] = __expf(v);
        out_trans[idx] = v;
    }
}

// ---------------- K1: recurrences ------------------------------------
// grid = 288. bid < 256: forward (1 batch/block, E column in regs).
//             bid >= 256: viterbi (8 batches/block, candidate-set pruned).
__global__ __launch_bounds__(128, 2) void k_recur(const float* __restrict__ emis,
                                                  const int* __restrict__ mask,
                                                  const float* __restrict__ trans) {
    extern __shared__ float transS[];   // 64KB, viterbi blocks only (row-major)
    const int j = threadIdx.x;
    const int w = j >> 5;
    const int lane = j & 31;

    if (blockIdx.x < BB) {
        // ================= forward: alpha'_j = log(sum_i p_i E_ij) + c + e
        __shared__ __align__(16) float fbuf[2][NN];
        __shared__ float csm[2];
        __shared__ unsigned char fmk[TT];
        const int b = blockIdx.x;
        const float* eb = emis + (size_t)b * TT * NN;

        for (int i = j; i < TT; i += NN)
            fmk[i] = (unsigned char)mask[(size_t)b * TT + i];

        unsigned long long E2[64];
        {
            const float* Ej = g_E + j;
            #pragma unroll
            for (int k = 0; k < 64; k++) {
                unsigned lo = __float_as_uint(Ej[(size_t)(2 * k) * NN]);
                unsigned hi = __float_as_uint(Ej[(size_t)(2 * k + 1) * NN]);
                E2[k] = (unsigned long long)lo | ((unsigned long long)hi << 32);
            }
        }

        float a = eb[j];
        float c = eb[0];
        float en = eb[NN + j];
        int sel = 0;
        __syncthreads();

        for (int t = 1; t < TT; t++) {
            fbuf[sel][j] = __expf(a - c);
            if (j == 0) csm[sel] = a;
            __syncthreads();
            float cn = csm[sel];

            unsigned long long acc[4] = {0ull, 0ull, 0ull, 0ull};
            const ulonglong2* pv = (const ulonglong2*)fbuf[sel];
            #pragma unroll
            for (int k = 0; k < 32; k++) {
                ulonglong2 v = pv[k];
                ffma2(acc[(2 * k) & 3], v.x, E2[2 * k]);
                ffma2(acc[(2 * k + 1) & 3], v.y, E2[2 * k + 1]);
            }
            float s = 0.f;
            #pragma unroll
            for (int q = 0; q < 4; q++) s += lo32(acc[q]) + hi32(acc[q]);

            float ec = en;
            if (t + 1 < TT) en = eb[(size_t)(t + 1) * NN + j];

            float nv = __logf(s) + c + ec;
            a = fmk[t] ? nv : a;
            c = cn;
            sel ^= 1;
        }

        fbuf[0][j] = __expf(a - c);
        __syncthreads();
        if (j < 32) {
            float4 v = ((const float4*)fbuf[0])[j];
            float ts = (v.x + v.y) + (v.z + v.w);
            #pragma unroll
            for (int o = 16; o; o >>= 1) ts += __shfl_xor_sync(0xffffffffu, ts, o);
            if (j == 0) g_lognorm[b] = __logf(ts) + c;
        }
    } else {
        // ================= viterbi, 8 batches, pruned candidate set.
        // Winner i* of max_i(a_i + T_ij) must have a_i >= A* - (Tmax-Tmin).
        const int bb = (blockIdx.x - BB) * 8;
        __shared__ __align__(16) float vbuf[2][8][NN];
        __shared__ unsigned swm[8][4];      // per-warp alpha maxima (ord space)
        __shared__ unsigned smsk[8][4];     // candidate ballots
        __shared__ unsigned char vmk[8][TT];
        __shared__ unsigned rmx[4], rmn[4];

        // load trans -> smem (row-major), tracking global min/max
        float tmx = -3.402823466e38f, tmn = 3.402823466e38f;
        for (int idx = j; idx < NN * NN / 4; idx += NN) {
            float4 v = ((const float4*)trans)[idx];
            ((float4*)transS)[idx] = v;
            tmx = fmaxf(tmx, fmaxf(fmaxf(v.x, v.y), fmaxf(v.z, v.w)));
            tmn = fminf(tmn, fminf(fminf(v.x, v.y), fminf(v.z, v.w)));
        }
        {
            unsigned ux = __reduce_max_sync(0xffffffffu, ordf(tmx));
            unsigned un = __reduce_min_sync(0xffffffffu, ordf(tmn));
            if (lane == 0) { rmx[w] = ux; rmn[w] = un; }
        }

        #pragma unroll
        for (int q = 0; q < 8; q++)
            for (int i = j; i < TT; i += NN)
                vmk[q][i] = (unsigned char)mask[(size_t)(bb + q) * TT + i];

        float a[8], en[8];
        #pragma unroll
        for (int q = 0; q < 8; q++) {
            const float* eq = emis + (size_t)(bb + q) * TT * NN;
            a[q] = eq[j];
            vbuf[0][q][j] = a[q];
            en[q] = eq[NN + j];
            unsigned u = __reduce_max_sync(0xffffffffu, ordf(a[q]));
            if (lane == 0) swm[q][w] = u;
        }
        __syncthreads();

        float Rr;
        {
            unsigned ax = max(max(rmx[0], rmx[1]), max(rmx[2], rmx[3]));
            unsigned an = min(min(rmn[0], rmn[1]), min(rmn[2], rmn[3]));
            Rr = (iordf(ax) - iordf(an)) + 0.01f;  // + rounding margin
        }

        unsigned char* bpb = g_bp + (size_t)bb * TT * NN;
        int sel = 0;
        const float NEGINF = -3.402823466e38f;

        for (int t = 1; t < TT; t++) {
            // phase 1: threshold + ballot candidate sets
            #pragma unroll
            for (int q = 0; q < 8; q++) {
                unsigned am = max(max(swm[q][0], swm[q][1]),
                                  max(swm[q][2], swm[q][3]));
                float thr = iordf(am) - Rr;
                unsigned mq = __ballot_sync(0xffffffffu, a[q] >= thr);
                if (lane == 0) smsk[q][w] = mq;
            }
            __syncthreads();

            // phase 2: evaluate candidates exactly (ascending i, strict > =
            // first argmax, bit-identical adds to the reference)
            #pragma unroll
            for (int q = 0; q < 8; q++) {
                float bst = NEGINF; int bi = 0;
                #pragma unroll
                for (int ww = 0; ww < 4; ww++) {
                    unsigned m = smsk[q][ww];
                    while (m) {
                        int i = ww * 32 + __ffs(m) - 1;
                        m &= m - 1;
                        float cv = vbuf[sel][q][i] + transS[i * NN + j];
                        if (cv > bst) { bst = cv; bi = i; }
                    }
                }
                float ec = en[q];
                if (t + 1 < TT)
                    en[q] = emis[(size_t)(bb + q) * TT * NN + (size_t)(t + 1) * NN + j];
                int mk = vmk[q][t];
                float nv = bst + ec;
                a[q] = mk ? nv : a[q];
                int bidx = mk ? bi : j;
                bpb[(size_t)q * TT * NN + (size_t)t * NN + j] = (unsigned char)bidx;
                vbuf[sel ^ 1][q][j] = a[q];
                unsigned u = __reduce_max_sync(0xffffffffu, ordf(a[q]));
                if (lane == 0) swm[q][w] = u;
            }
            sel ^= 1;
            __syncthreads();
        }

        // last_tag: warp w handles batches w and w+4 (first-index argmax)
        #pragma unroll
        for (int r = 0; r < 2; r++) {
            int q = w + 4 * r;
            float4 v = ((const float4*)vbuf[sel][q])[lane];
            float best = v.x; int bi = 4 * lane;
            if (v.y > best) { best = v.y; bi = 4 * lane + 1; }
            if (v.z > best) { best = v.z; bi = 4 * lane + 2; }
            if (v.w > best) { best = v.w; bi = 4 * lane + 3; }
            unsigned u = ordf(best);
            unsigned wm = __reduce_max_sync(0xffffffffu, u);
            unsigned bal = __ballot_sync(0xffffffffu, u == wm);
            int src = __ffs(bal) - 1;
            bi = __shfl_sync(0xffffffffu, bi, src);
            if (lane == 0) g_lasttag[bb + q] = bi;
        }
    }
}

// ---------------- K2: traceback + score + ll ------------------------
// One block per batch. 128 threads: load 64KB bp slab into smem + compute
// the sequence score. Thread 0: chase backpointers (LDS.U8 chain).
__global__ __launch_bounds__(128) void k_traceback(const float* __restrict__ emis,
                                                   const int* __restrict__ tags,
                                                   const int* __restrict__ mask,
                                                   const float* __restrict__ trans,
                                                   float* __restrict__ out_ll,
                                                   float* __restrict__ out_tags) {
    extern __shared__ unsigned char sbp[];  // 64KB
    __shared__ float sred[4];
    const int b = blockIdx.x;
    const int tid = threadIdx.x;

    const float4* src = (const float4*)(g_bp + (size_t)b * TT * NN);
    #pragma unroll
    for (int i = 0; i < 32; i++)
        ((float4*)sbp)[tid + i * 128] = src[tid + i * 128];

    // sequence score (gather + block reduce), overlaps the slab load
    {
        const float* eb = emis + (size_t)b * TT * NN;
        const int* tb = tags + (size_t)b * TT;
        const int* mb = mask + (size_t)b * TT;
        float acc = 0.f;
        for (int t = tid; t < TT; t += 128) {
            int tg = tb[t];
            float mf = (float)mb[t];
            float u = eb[(size_t)t * NN + tg] * mf;
            float bi = 0.f;
            if (t > 0) {
                int tp = tb[t - 1];
                bi = trans[tp * NN + tg] * mf;
            }
            acc += u + bi;
        }
        #pragma unroll
        for (int o = 16; o; o >>= 1) acc += __shfl_xor_sync(0xffffffffu, acc, o);
        if ((tid & 31) == 0) sred[tid >> 5] = acc;
    }
    __syncthreads();

    if (tid == 0) {
        float score = sred[0] + sred[1] + sred[2] + sred[3];
        out_ll[b] = score - g_lognorm[b];

        float* ot = out_tags + (size_t)b * TT;
        int tag = g_lasttag[b];
        ot[TT - 1] = (float)tag;
        for (int t = TT - 2; t >= 0; t--) {
            tag = sbp[(t + 1) * NN + tag];
            ot[t] = (float)tag;
        }
    }
}

// ---------------- launch ---------------------------------------------
extern "C" void kernel_launch(void* const* d_in, const int* in_sizes, int n_in,
                              void* d_out, int out_size) {
    const float* emis  = (const float*)d_in[0];
    const int*   tags  = (const int*)d_in[1];
    const int*   mask  = (const int*)d_in[2];
    const float* trans = (const float*)d_in[3];
    float* out = (float*)d_out;

    float* out_ll    = out;
    float* out_trans = out + BB;
    float* out_tags  = out + BB + NN * NN;

    const int SM64 = NN * NN * (int)sizeof(float);   // 64KB
    cudaFuncSetAttribute(k_recur, cudaFuncAttributeMaxDynamicSharedMemorySize, SM64);
    cudaFuncSetAttribute(k_traceback, cudaFuncAttributeMaxDynamicSharedMemorySize, SM64);

    k_prep<<<(NN * NN + 255) / 256, 256>>>(trans, out_trans);
    k_recur<<<BB + BB / 8, 128, SM64>>>(emis, mask, trans);
    k_traceback<<<BB, 128, SM64>>>(emis, tags, mask, trans, out_ll, out_tags);
}

// round 10
// speedup vs baseline: 2.2269x; 2.2269x over previous
#include <cuda_runtime.h>
#include <cstdint>

// Problem constants
#define BB 256
#define TT 512
#define NN 128

// ---------------- device scratch ----------------
__device__ float g_E[NN * NN];                 // exp(trans)
__device__ float g_lognorm[BB];
__device__ unsigned char g_bp[(size_t)BB * TT * NN]; // backpointers, 16.7 MB
__device__ int   g_lasttag[BB];

__device__ __forceinline__ unsigned ordf(float f) {
    unsigned u = __float_as_uint(f);
    return u ^ (((int)u >> 31) | 0x80000000u);
}

__device__ __forceinline__ void ffma2(unsigned long long& d,
                                      unsigned long long a,
                                      unsigned long long b) {
    asm("fma.rn.f32x2 %0, %1, %2, %0;" : "+l"(d) : "l"(a), "l"(b));
}

__device__ __forceinline__ unsigned long long add2(unsigned long long a,
                                                   unsigned long long b) {
    unsigned long long d;
    asm("add.rn.f32x2 %0, %1, %2;" : "=l"(d) : "l"(a), "l"(b));
    return d;
}

__device__ __forceinline__ float lo32(unsigned long long v) {
    return __uint_as_float((unsigned)v);
}
__device__ __forceinline__ float hi32(unsigned long long v) {
    return __uint_as_float((unsigned)(v >> 32));
}

// ---------------- K0: prep -----------------------------------------
__global__ void k_prep(const float* __restrict__ trans, float* __restrict__ out_trans) {
    int idx = blockIdx.x * 256 + threadIdx.x;
    if (idx < NN * NN) {
        float v = trans[idx];
        g_E[idx] = __expf(v);
        out_trans[idx] = v;
    }
}

// ---------------- K1: fused recurrences, 2 batches per block ---------
// grid = 256. blockIdx&1 == 0 -> forward (log-norm), == 1 -> viterbi.
// (Parity split is the empirically fastest placement: R7=496us vs
//  half-split R8=561us. Do not change without fresh evidence.)
// Each block handles batches b0=2*(blockIdx>>1), b1=b0+1.
__global__ __launch_bounds__(128, 2) void k_recur(const float* __restrict__ emis,
                                                  const int* __restrict__ mask,
                                                  const float* __restrict__ trans) {
    extern __shared__ float transS[];   // 64KB, viterbi blocks only (row-major trans)

    const int type = blockIdx.x & 1;
    const int p = blockIdx.x >> 1;
    const int b0 = 2 * p;
    const int b1 = b0 + 1;
    const int j = threadIdx.x;

    __shared__ __align__(16) float buf[2][2][NN];   // [sel][batch][state]
    __shared__ float csm[2][2];
    __shared__ int smask[2][TT];

    const float* e0 = emis + (size_t)b0 * TT * NN;
    const float* e1 = emis + (size_t)b1 * TT * NN;

    for (int i = j; i < TT; i += NN) {
        smask[0][i] = mask[(size_t)b0 * TT + i];
        smask[1][i] = mask[(size_t)b1 * TT + i];
    }

    if (type == 0) {
        // forward: alpha'_j = log(sum_i p_i * E_ij) + c + emit
        unsigned long long E2[64];
        {
            const float* Ej = g_E + j;
            #pragma unroll
            for (int k = 0; k < 64; k++) {
                unsigned lo = __float_as_uint(Ej[(size_t)(2 * k) * NN]);
                unsigned hi = __float_as_uint(Ej[(size_t)(2 * k + 1) * NN]);
                E2[k] = (unsigned long long)lo | ((unsigned long long)hi << 32);
            }
        }

        float a0 = e0[j],  a1 = e1[j];
        float c0 = e0[0],  c1 = e1[0];
        float en0 = e0[NN + j], en1 = e1[NN + j];
        int sel = 0;
        __syncthreads();             // smask ready

        for (int t = 1; t < TT; t++) {
            buf[sel][0][j] = __expf(a0 - c0);
            buf[sel][1][j] = __expf(a1 - c1);
            if (j == 0) { csm[sel][0] = a0; csm[sel][1] = a1; }
            __syncthreads();
            float c0n = csm[sel][0], c1n = csm[sel][1];

            unsigned long long acc0[4] = {0ull, 0ull, 0ull, 0ull};
            unsigned long long acc1[4] = {0ull, 0ull, 0ull, 0ull};
            const ulonglong2* p0 = (const ulonglong2*)buf[sel][0];
            const ulonglong2* p1 = (const ulonglong2*)buf[sel][1];
            #pragma unroll
            for (int k = 0; k < 32; k++) {
                ulonglong2 v0 = p0[k];
                ulonglong2 v1 = p1[k];
                ffma2(acc0[(2 * k) & 3], v0.x, E2[2 * k]);
                ffma2(acc0[(2 * k + 1) & 3], v0.y, E2[2 * k + 1]);
                ffma2(acc1[(2 * k) & 3], v1.x, E2[2 * k]);
                ffma2(acc1[(2 * k + 1) & 3], v1.y, E2[2 * k + 1]);
            }
            float s0 = 0.f, s1 = 0.f;
            #pragma unroll
            for (int q = 0; q < 4; q++) {
                s0 += lo32(acc0[q]) + hi32(acc0[q]);
                s1 += lo32(acc1[q]) + hi32(acc1[q]);
            }

            float ec0 = en0, ec1 = en1;
            if (t + 1 < TT) {
                en0 = e0[(size_t)(t + 1) * NN + j];
                en1 = e1[(size_t)(t + 1) * NN + j];
            }

            float n0 = __logf(s0) + c0 + ec0;
            float n1 = __logf(s1) + c1 + ec1;
            a0 = smask[0][t] ? n0 : a0;
            a1 = smask[1][t] ? n1 : a1;
            c0 = c0n; c1 = c1n;
            sel ^= 1;
        }

        // final logsumexp, one warp per batch
        buf[0][0][j] = __expf(a0 - c0);
        buf[0][1][j] = __expf(a1 - c1);
        __syncthreads();
        const int wid = j >> 5;
        if (wid < 2) {
            const int l = j & 31;
            float4 v = ((const float4*)buf[0][wid])[l];
            float ts = (v.x + v.y) + (v.z + v.w);
            #pragma unroll
            for (int o = 16; o; o >>= 1) ts += __shfl_xor_sync(0xffffffffu, ts, o);
            if (l == 0) {
                int b = wid ? b1 : b0;
                float c = wid ? c1 : c0;
                g_lognorm[b] = __logf(ts) + c;
            }
        }
    } else {
        // viterbi: alpha'_j = max_i(a_i + T_ij) + emit, with backpointers.
        // Contiguous group maxima m[q] over i in [16q, 16q+16), then rescan
        // the first group attaining the max for the exact first argmax.
        unsigned long long T2[64];
        {
            const float* Tj = trans + j;
            #pragma unroll
            for (int k = 0; k < 64; k++) {
                unsigned lo = __float_as_uint(Tj[(size_t)(2 * k) * NN]);
                unsigned hi = __float_as_uint(Tj[(size_t)(2 * k + 1) * NN]);
                T2[k] = (unsigned long long)lo | ((unsigned long long)hi << 32);
            }
        }
        // row-major trans copy in smem for the rescan
        for (int idx = j; idx < NN * NN / 4; idx += NN)
            ((float4*)transS)[idx] = ((const float4*)trans)[idx];

        unsigned char* bp0 = g_bp + (size_t)b0 * TT * NN;
        unsigned char* bp1 = g_bp + (size_t)b1 * TT * NN;
        float a0 = e0[j], a1 = e1[j];
        buf[0][0][j] = a0;
        buf[0][1][j] = a1;
        float en0 = e0[NN + j], en1 = e1[NN + j];
        int sel = 0;
        const float NEGINF = -3.402823466e38f;
        __syncthreads();             // buf[0] + smask + transS ready

        for (int t = 1; t < TT; t++) {
            float m0[8], m1[8];
            #pragma unroll
            for (int q = 0; q < 8; q++) { m0[q] = NEGINF; m1[q] = NEGINF; }
            const ulonglong2* p0 = (const ulonglong2*)buf[sel][0];
            const ulonglong2* p1 = (const ulonglong2*)buf[sel][1];
            #pragma unroll
            for (int k = 0; k < 32; k++) {           // cands 4k..4k+3, group k>>2
                ulonglong2 v0 = p0[k];
                ulonglong2 v1 = p1[k];
                unsigned long long w00 = add2(v0.x, T2[2 * k]);
                unsigned long long w01 = add2(v0.y, T2[2 * k + 1]);
                unsigned long long w10 = add2(v1.x, T2[2 * k]);
                unsigned long long w11 = add2(v1.y, T2[2 * k + 1]);
                const int q = k >> 2;
                m0[q] = fmaxf(m0[q], lo32(w00));
                m0[q] = fmaxf(m0[q], hi32(w00));
                m0[q] = fmaxf(m0[q], lo32(w01));
                m0[q] = fmaxf(m0[q], hi32(w01));
                m1[q] = fmaxf(m1[q], lo32(w10));
                m1[q] = fmaxf(m1[q], hi32(w10));
                m1[q] = fmaxf(m1[q], lo32(w11));
                m1[q] = fmaxf(m1[q], hi32(w11));
            }
            float bm0 = fmaxf(fmaxf(fmaxf(m0[0], m0[1]), fmaxf(m0[2], m0[3])),
                              fmaxf(fmaxf(m0[4], m0[5]), fmaxf(m0[6], m0[7])));
            float bm1 = fmaxf(fmaxf(fmaxf(m1[0], m1[1]), fmaxf(m1[2], m1[3])),
                              fmaxf(fmaxf(m1[4], m1[5]), fmaxf(m1[6], m1[7])));

            // first group attaining the max
            int g0 = 7, g1 = 7;
            #pragma unroll
            for (int q = 6; q >= 0; q--) {
                g0 = (m0[q] == bm0) ? q : g0;
                g1 = (m1[q] == bm1) ? q : g1;
            }

            // rescan winning group: first index with candidate == bm
            int u0 = 15, u1 = 15;
            {
                const float* al0 = buf[sel][0] + 16 * g0;
                const float* al1 = buf[sel][1] + 16 * g1;
                float av0[16], av1[16];
                #pragma unroll
                for (int r = 0; r < 4; r++) {
                    float4 x0 = ((const float4*)al0)[r];
                    float4 x1 = ((const float4*)al1)[r];
                    av0[4 * r] = x0.x; av0[4 * r + 1] = x0.y;
                    av0[4 * r + 2] = x0.z; av0[4 * r + 3] = x0.w;
                    av1[4 * r] = x1.x; av1[4 * r + 1] = x1.y;
                    av1[4 * r + 2] = x1.z; av1[4 * r + 3] = x1.w;
                }
                const float* ts0 = transS + (size_t)(16 * g0) * NN + j;
                const float* ts1 = transS + (size_t)(16 * g1) * NN + j;
                #pragma unroll
                for (int r = 15; r >= 0; r--) {
                    float c0v = av0[r] + ts0[(size_t)r * NN];
                    float c1v = av1[r] + ts1[(size_t)r * NN];
                    u0 = (c0v == bm0) ? r : u0;
                    u1 = (c1v == bm1) ? r : u1;
                }
            }

            float ec0 = en0, ec1 = en1;
            if (t + 1 < TT) {
                en0 = e0[(size_t)(t + 1) * NN + j];
                en1 = e1[(size_t)(t + 1) * NN + j];
            }

            int msk0 = smask[0][t], msk1 = smask[1][t];
            float n0 = bm0 + ec0;
            float n1 = bm1 + ec1;
            a0 = msk0 ? n0 : a0;
            a1 = msk1 ? n1 : a1;
            int v0i = msk0 ? (16 * g0 + u0) : j;
            int v1i = msk1 ? (16 * g1 + u1) : j;
            bp0[(size_t)t * NN + j] = (unsigned char)v0i;
            bp1[(size_t)t * NN + j] = (unsigned char)v1i;
            buf[sel ^ 1][0][j] = a0;
            buf[sel ^ 1][1][j] = a1;
            sel ^= 1;
            __syncthreads();
        }

        // last_tag per batch: one warp each (first-index argmax)
        const int wid = j >> 5;
        if (wid < 2) {
            const int l = j & 31;
            float4 v = ((const float4*)buf[sel][wid])[l];
            float best = v.x; int bi = 4 * l;
            if (v.y > best) { best = v.y; bi = 4 * l + 1; }
            if (v.z > best) { best = v.z; bi = 4 * l + 2; }
            if (v.w > best) { best = v.w; bi = 4 * l + 3; }
            unsigned u = ordf(best);
            unsigned wm = __reduce_max_sync(0xffffffffu, u);
            unsigned bal = __ballot_sync(0xffffffffu, u == wm);
            int src = __ffs(bal) - 1;
            bi = __shfl_sync(0xffffffffu, bi, src);
            if (l == 0) g_lasttag[wid ? b1 : b0] = bi;
        }
    }
}

// ---------------- K2: traceback + score + ll ------------------------
// One block per batch. All 128 threads: load 64KB bp slab into smem and
// compute the sequence score (gather overlaps slab load). Thread 0: chase.
__global__ __launch_bounds__(128) void k_traceback(const float* __restrict__ emis,
                                                   const int* __restrict__ tags,
                                                   const int* __restrict__ mask,
                                                   const float* __restrict__ trans,
                                                   float* __restrict__ out_ll,
                                                   float* __restrict__ out_tags) {
    extern __shared__ unsigned char sbp[];  // 64KB
    __shared__ float sred[4];
    const int b = blockIdx.x;
    const int tid = threadIdx.x;

    const float4* src = (const float4*)(g_bp + (size_t)b * TT * NN);
    #pragma unroll
    for (int i = 0; i < 32; i++)
        ((float4*)sbp)[tid + i * 128] = src[tid + i * 128];

    // sequence score (gather + block reduce)
    {
        const float* eb = emis + (size_t)b * TT * NN;
        const int* tb = tags + (size_t)b * TT;
        const int* mb = mask + (size_t)b * TT;
        float acc = 0.f;
        for (int t = tid; t < TT; t += 128) {
            int tg = tb[t];
            float mf = (float)mb[t];
            float u = eb[(size_t)t * NN + tg] * mf;
            float bi = 0.f;
            if (t > 0) {
                int tp = tb[t - 1];
                bi = trans[tp * NN + tg] * mf;
            }
            acc += u + bi;
        }
        #pragma unroll
        for (int o = 16; o; o >>= 1) acc += __shfl_xor_sync(0xffffffffu, acc, o);
        if ((tid & 31) == 0) sred[tid >> 5] = acc;
    }
    __syncthreads();

    if (tid == 0) {
        float score = sred[0] + sred[1] + sred[2] + sred[3];
        out_ll[b] = score - g_lognorm[b];

        float* ot = out_tags + (size_t)b * TT;
        int tag = g_lasttag[b];
        ot[TT - 1] = (float)tag;
        for (int t = TT - 2; t >= 0; t--) {
            tag = sbp[(t + 1) * NN + tag];
            ot[t] = (float)tag;
        }
    }
}

// ---------------- launch ---------------------------------------------
extern "C" void kernel_launch(void* const* d_in, const int* in_sizes, int n_in,
                              void* d_out, int out_size) {
    const float* emis  = (const float*)d_in[0];
    const int*   tags  = (const int*)d_in[1];
    const int*   mask  = (const int*)d_in[2];
    const float* trans = (const float*)d_in[3];
    float* out = (float*)d_out;

    float* out_ll    = out;
    float* out_trans = out + BB;
    float* out_tags  = out + BB + NN * NN;

    const int SM64 = NN * NN * (int)sizeof(float);   // 64KB
    cudaFuncSetAttribute(k_recur, cudaFuncAttributeMaxDynamicSharedMemorySize, SM64);
    cudaFuncSetAttribute(k_traceback, cudaFuncAttributeMaxDynamicSharedMemorySize, SM64);

    k_prep<<<(NN * NN + 255) / 256, 256>>>(trans, out_trans);
    k_recur<<<BB, 128, SM64>>>(emis, mask, trans);
    k_traceback<<<BB, 128, SM64>>>(emis, tags, mask, trans, out_ll, out_tags);
}